// round 1
// baseline (speedup 1.0000x reference)
#include <cuda_runtime.h>
#include <cuda_fp16.h>

// ---------------- problem constants ----------------
#define S_LEN   4096
#define HID     2048
#define NCTA    148
#define NTHR    256
#define U_MAX   14                       // max hidden units per CTA (124 CTAs get 14, 24 get 13)
#define W_SMEM_HALVES (U_MAX * 4 * 2048) // fp16 weight elements in smem
#define SMEM_BYTES (W_SMEM_HALVES * 2 + 64 * 4)
#define SH_TOT  (S_LEN * HID)            // size of "stacked" output block

// ---------------- device scratch (no allocations allowed) ----------------
__device__ __half   g_wh[(size_t)HID * 4 * 2048]; // transposed fp16 recurrent weights [j][g][r]
__device__ float    g_c[S_LEN];                    // conv sigmoid scalar per step
__device__ float    g_w0[4 * HID];                 // input-scalar row weights [j*4+g]
__device__ float    g_bias[4 * HID];               // gate biases            [j*4+g]
__device__ unsigned g_bar;                         // monotonic grid barrier counter

// ---------------- small helpers ----------------
__device__ __forceinline__ unsigned long long pk2(float x, float y) {
    unsigned long long r; asm("mov.b64 %0,{%1,%2};" : "=l"(r) : "f"(x), "f"(y)); return r;
}
__device__ __forceinline__ void upk2(unsigned long long v, float &x, float &y) {
    asm("mov.b64 {%0,%1},%2;" : "=f"(x), "=f"(y) : "l"(v));
}
__device__ __forceinline__ void fma2(unsigned long long &a, unsigned long long b, unsigned long long c) {
    asm("fma.rn.f32x2 %0,%1,%2,%0;" : "+l"(a) : "l"(b), "l"(c));   // 2 fp32 FMAs / instr
}
__device__ __forceinline__ void add2(unsigned long long &a, unsigned long long b) {
    asm("add.rn.f32x2 %0,%0,%1;" : "+l"(a) : "l"(b));
}
__device__ __forceinline__ unsigned bar_ld(const unsigned *p) {
    unsigned v; asm volatile("ld.acquire.gpu.global.u32 %0,[%1];" : "=r"(v) : "l"(p)); return v;
}
__device__ __forceinline__ void bar_red(unsigned *p) {
    asm volatile("red.release.gpu.global.add.u32 [%0],1;" :: "l"(p));
}
__device__ __forceinline__ float sigm(float x)      { return 1.f / (1.f + __expf(-x)); }
__device__ __forceinline__ float tanh_fast(float x) { return 2.f / (1.f + __expf(-2.f * x)) - 1.f; }

// ---------------- prep: transpose + fp16-convert recurrent weights ----------------
// g_wh[((j*4+g)*2048)+r] = (half) w_gates[(1+r)*8192 + g*2048 + j]
__global__ void prep_convert(const float *__restrict__ wg) {
    int idx = blockIdx.x * 256 + threadIdx.x;       // 0 .. 16,777,215
    int r = idx & 2047;
    int d = idx >> 11;
    int g = d & 3;
    int j = d >> 2;
    g_wh[idx] = __float2half(wg[(size_t)(1 + r) * (4 * HID) + g * HID + j]);
}

// ---------------- prep: conv scalars, row-0 weights, biases, barrier reset ----------------
__global__ void prep_small(const float *__restrict__ in, const float *__restrict__ cw,
                           const float *__restrict__ cb, const float *__restrict__ wg,
                           const float *__restrict__ bg) {
    int tid = blockIdx.x * blockDim.x + threadIdx.x;
    if (tid < S_LEN) {
        float a = in[tid * 4 + 0] * cw[0] + in[tid * 4 + 1] * cw[1]
                + in[tid * 4 + 2] * cw[2] + in[tid * 4 + 3] * cw[3] + cb[0];
        g_c[tid] = 1.f / (1.f + __expf(-a));
    }
    for (int k = tid; k < 4 * HID; k += gridDim.x * blockDim.x) {
        int g = k & 3, j = k >> 2;
        g_w0[k]   = wg[g * HID + j];      // row 0 of w_gates
        g_bias[k] = bg[g * HID + j];
    }
    if (tid == 0 && blockIdx.x == 0) g_bar = 0;
}

// ---------------- main persistent LSTM kernel ----------------
__global__ __launch_bounds__(NTHR, 1) void lstm_main(float *__restrict__ out) {
    extern __shared__ unsigned char smem[];
    __half *wsm = (__half *)smem;
    float  *red = (float *)(smem + (size_t)W_SMEM_HALVES * 2);   // 64 floats: per-dot reductions

    const int b = blockIdx.x;
    const int ustart = b * 13 + min(b, 124);     // 2048 = 124*14 + 24*13
    const int U = (b < 124) ? 14 : 13;
    const int D = U * 4;                          // dot products owned by this CTA
    const int tid  = threadIdx.x;
    const int w    = tid >> 5;
    const int lane = tid & 31;

    // Stage this CTA's weight block (contiguous in g_wh) into shared memory.
    {
        const uint4 *src = (const uint4 *)(g_wh + (size_t)ustart * 4 * 2048);
        uint4 *dst = (uint4 *)wsm;
        const int nv = U * 4 * 2048 / 8;
        for (int i = tid; i < nv; i += NTHR) dst[i] = src[i];
    }

    float w0r[4], br[4], cx = 0.f;
    if (tid < U) {
        #pragma unroll
        for (int g = 0; g < 4; g++) {
            w0r[g] = g_w0[(ustart + tid) * 4 + g];
            br[g]  = g_bias[(ustart + tid) * 4 + g];
        }
    }
    __syncthreads();

    unsigned long long hxp[32];   // 64 hx values per lane, packed as f32x2 pairs

    for (int t = 0; t < S_LEN; t++) {
        // ---- load hx(t-1): lane covers elements i*256 + lane*8 .. +7 ----
        if (t == 0) {
            #pragma unroll
            for (int k = 0; k < 32; k++) hxp[k] = 0ULL;
        } else {
            const float4 *hrow = (const float4 *)(out + (size_t)(t - 1) * HID);
            #pragma unroll
            for (int i = 0; i < 8; i++) {
                float4 a = hrow[i * 64 + lane * 2];
                float4 c = hrow[i * 64 + lane * 2 + 1];
                hxp[i * 4 + 0] = pk2(a.x, a.y);
                hxp[i * 4 + 1] = pk2(a.z, a.w);
                hxp[i * 4 + 2] = pk2(c.x, c.y);
                hxp[i * 4 + 3] = pk2(c.z, c.w);
            }
        }

        // ---- dot products: warp w handles dots d = w, w+8, w+16, ... ----
        for (int d = w; d < D; d += 8) {
            unsigned long long a0 = 0, a1 = 0, a2 = 0, a3 = 0;
            const uint4 *wp = (const uint4 *)(wsm + (size_t)d * 2048);
            #pragma unroll
            for (int i = 0; i < 8; i++) {
                uint4 wv = wp[i * 32 + lane];           // 8 fp16 weights (LDS.128, conflict-free)
                float2 f0 = __half22float2(*(__half2 *)&wv.x);
                float2 f1 = __half22float2(*(__half2 *)&wv.y);
                float2 f2 = __half22float2(*(__half2 *)&wv.z);
                float2 f3 = __half22float2(*(__half2 *)&wv.w);
                fma2(a0, pk2(f0.x, f0.y), hxp[i * 4 + 0]);
                fma2(a1, pk2(f1.x, f1.y), hxp[i * 4 + 1]);
                fma2(a2, pk2(f2.x, f2.y), hxp[i * 4 + 2]);
                fma2(a3, pk2(f3.x, f3.y), hxp[i * 4 + 3]);
            }
            add2(a0, a1); add2(a2, a3); add2(a0, a2);
            float sl, sh; upk2(a0, sl, sh);
            float s = sl + sh;
            #pragma unroll
            for (int off = 16; off; off >>= 1) s += __shfl_xor_sync(0xffffffffu, s, off);
            if (lane == 0) red[d] = s;
        }
        __syncthreads();

        // ---- epilogue: one thread per hidden unit ----
        if (tid < U) {
            float ct = g_c[t];
            float af = red[tid * 4 + 0] + ct * w0r[0] + br[0];
            float ai = red[tid * 4 + 1] + ct * w0r[1] + br[1];
            float ag = red[tid * 4 + 2] + ct * w0r[2] + br[2];
            float ao = red[tid * 4 + 3] + ct * w0r[3] + br[3];
            float f  = sigm(af);
            float ii = sigm(ai);
            float gg = tanh_fast(ag);
            float oo = sigm(ao);
            cx = f * cx + ii * gg;
            float h = oo * tanh_fast(cx);
            int j = ustart + tid;
            __stcg(out + (size_t)t * HID + j, h);     // bypass L1 (other SMs read via L2)
            if (t == S_LEN - 1) {
                out[SH_TOT + j]       = h;            // final hx
                out[SH_TOT + HID + j] = cx;           // final cx
            }
        }
        __syncthreads();

        // ---- grid barrier: monotonic counter, release-arrive + acquire-spin ----
        if (tid == 0) {
            __threadfence();
            bar_red(&g_bar);
            const unsigned tgt = (unsigned)NCTA * (unsigned)(t + 1);
            while (bar_ld(&g_bar) < tgt) { }
        }
        __syncthreads();
    }
}

// ---------------- launch ----------------
extern "C" void kernel_launch(void *const *d_in, const int *in_sizes, int n_in,
                              void *d_out, int out_size) {
    const float *inputs = nullptr, *cw = nullptr, *cb = nullptr, *wg = nullptr, *bg = nullptr;
    for (int i = 0; i < n_in; i++) {
        switch (in_sizes[i]) {
            case S_LEN * 4:        inputs = (const float *)d_in[i]; break;   // 16384
            case 4:                cw     = (const float *)d_in[i]; break;
            case 1:                cb     = (const float *)d_in[i]; break;
            case 2049 * 4 * HID:   wg     = (const float *)d_in[i]; break;   // 16,785,408
            case 4 * HID:          bg     = (const float *)d_in[i]; break;   // 8192
        }
    }
    float *out = (float *)d_out;

    static bool attr_set = false;
    if (!attr_set) {
        cudaFuncSetAttribute(lstm_main, cudaFuncAttributeMaxDynamicSharedMemorySize, SMEM_BYTES);
        attr_set = true;
    }

    prep_convert<<<(HID * 4 * 2048) / 256, 256>>>(wg);
    prep_small<<<16, 256>>>(inputs, cw, cb, wg, bg);
    lstm_main<<<NCTA, NTHR, SMEM_BYTES>>>(out);
}

// round 2
// speedup vs baseline: 1.3397x; 1.3397x over previous
#include <cuda_runtime.h>
#include <cuda_fp16.h>

// ---------------- problem constants ----------------
#define S_LEN   4096
#define HID     2048
#define NCTA    148
#define NTHR    256
#define DPAD    56                        // dots per CTA, padded (4 gates x 14 units max)
#define U2_PER_CTA (8 * 16 * 7 * 32)      // 28672 uint2 (8 warps x 16 chunks x 7 ngroups x 32 lanes)
#define SMEM_W_BYTES (U2_PER_CTA * 8)     // 229376 B of fragment-ordered fp16 weights
#define SMEM_BYTES (SMEM_W_BYTES + 8 * DPAD * 4)   // + per-warp partial sums
#define SH_TOT  (S_LEN * HID)

// ---------------- device scratch ----------------
__device__ uint2    g_wfrag[(size_t)NCTA * U2_PER_CTA];  // B-fragment-ordered fp16 weights
__device__ float    g_c[S_LEN];                           // conv sigmoid scalar per step
__device__ float    g_w0[HID * 4];                        // input-scalar weights [j*4+g]
__device__ float    g_bias[HID * 4];                      // biases              [j*4+g]
__device__ unsigned g_bar;                                // monotonic grid barrier

// ---------------- helpers ----------------
__device__ __forceinline__ unsigned bar_ld(const unsigned *p) {
    unsigned v; asm volatile("ld.acquire.gpu.global.u32 %0,[%1];" : "=r"(v) : "l"(p)); return v;
}
__device__ __forceinline__ void bar_red(unsigned *p) {
    asm volatile("red.release.gpu.global.add.u32 [%0],1;" :: "l"(p));
}
__device__ __forceinline__ float sigm(float x)      { return 1.f / (1.f + __expf(-x)); }
__device__ __forceinline__ float tanh_fast(float x) { return 2.f / (1.f + __expf(-2.f * x)) - 1.f; }

// ---------------- prep: build B-fragment-ordered fp16 weight image ----------------
// For CTA b, warp w, chunk c, ngroup ng, lane l (one uint2 = 2 half2):
//   dot d = ng*8 + l/4   (d = local_unit*4 + gate)
//   k0    = (w*16+c)*16 + (l%4)*2
//   v.x = {W[d][k0], W[d][k0+1]},  v.y = {W[d][k0+8], W[d][k0+9]}
// where W[d][k] = w_gates[(1+k)*8192 + gate*2048 + (ustart + d/4)], zero-padded for d >= 4U.
__global__ void prep_frag(const float *__restrict__ wg) {
    size_t idx = (size_t)blockIdx.x * 256 + threadIdx.x;
    if (idx >= (size_t)NCTA * U2_PER_CTA) return;
    int l  = (int)(idx & 31);
    int ng = (int)((idx >> 5) % 7);
    size_t r = idx / (7 * 32);
    int c = (int)(r & 15); r >>= 4;
    int w = (int)(r & 7);  int b = (int)(r >> 3);
    int ustart = b * 13 + min(b, 124);
    int U = (b < 124) ? 14 : 13;
    int d  = ng * 8 + (l >> 2);
    int k0 = ((w * 16 + c) << 4) + ((l & 3) << 1);
    uint2 v = make_uint2(0u, 0u);
    if (d < 4 * U) {
        int j = ustart + (d >> 2);
        int g = d & 3;
        const float *base = wg + (size_t)g * HID + j;
        float w00 = base[(size_t)(1 + k0) * (4 * HID)];
        float w01 = base[(size_t)(2 + k0) * (4 * HID)];
        float w10 = base[(size_t)(9 + k0) * (4 * HID)];
        float w11 = base[(size_t)(10 + k0) * (4 * HID)];
        __half2 lo = __floats2half2_rn(w00, w01);
        __half2 hi = __floats2half2_rn(w10, w11);
        v.x = *(unsigned *)&lo;
        v.y = *(unsigned *)&hi;
    }
    g_wfrag[idx] = v;
}

// ---------------- prep: conv scalars, row-0 weights, biases, barrier reset ----------------
__global__ void prep_small(const float *__restrict__ in, const float *__restrict__ cw,
                           const float *__restrict__ cb, const float *__restrict__ wg,
                           const float *__restrict__ bg) {
    int tid = blockIdx.x * blockDim.x + threadIdx.x;
    if (tid < S_LEN) {
        float a = in[tid * 4 + 0] * cw[0] + in[tid * 4 + 1] * cw[1]
                + in[tid * 4 + 2] * cw[2] + in[tid * 4 + 3] * cw[3] + cb[0];
        g_c[tid] = 1.f / (1.f + __expf(-a));
    }
    for (int k = tid; k < 4 * HID; k += gridDim.x * blockDim.x) {
        int g = k & 3, j = k >> 2;
        g_w0[k]   = wg[g * HID + j];
        g_bias[k] = bg[g * HID + j];
    }
    if (tid == 0 && blockIdx.x == 0) g_bar = 0;
}

// ---------------- main persistent LSTM kernel (tensor-core matvec) ----------------
__global__ __launch_bounds__(NTHR, 1) void lstm_main(float *__restrict__ out) {
    extern __shared__ unsigned char smem[];
    uint2 *ws  = (uint2 *)smem;
    float *red = (float *)(smem + SMEM_W_BYTES);   // [8 warps][DPAD] partial dots

    const int b = blockIdx.x;
    const int ustart = b * 13 + min(b, 124);
    const int U = (b < 124) ? 14 : 13;
    const int tid  = threadIdx.x;
    const int w    = tid >> 5;
    const int lane = tid & 31;

    // Stage this CTA's fragment-ordered weights into shared memory.
    {
        const uint4 *src = (const uint4 *)(g_wfrag + (size_t)b * U2_PER_CTA);
        uint4 *dst = (uint4 *)ws;
        for (int i = tid; i < U2_PER_CTA / 2; i += NTHR) dst[i] = src[i];
    }

    float w0r[4], br[4], cx = 0.f;
    if (tid < U) {
        #pragma unroll
        for (int g = 0; g < 4; g++) {
            w0r[g] = g_w0[(ustart + tid) * 4 + g];
            br[g]  = g_bias[(ustart + tid) * 4 + g];
        }
    }
    __syncthreads();

    const uint2 *wp = ws + w * (16 * 7 * 32) + lane;      // per-warp B-fragment base
    const int aoff = w * 128 + (lane & 3);                // hx float2 offset for A fragments

    for (int t = 0; t < S_LEN; t++) {
        // ---- A fragments: hx(t-1) chunk data, f32x2 -> f16x2 (single F2FP each) ----
        unsigned alo[16], ahi[16];
        if (t == 0) {
            #pragma unroll
            for (int c = 0; c < 16; c++) { alo[c] = 0u; ahi[c] = 0u; }
        } else {
            const float2 *hb = (const float2 *)(out + (size_t)(t - 1) * HID) + aoff;
            float2 lo[16], hi[16];
            #pragma unroll
            for (int c = 0; c < 16; c++) { lo[c] = hb[c * 8]; hi[c] = hb[c * 8 + 4]; }
            #pragma unroll
            for (int c = 0; c < 16; c++) {
                __half2 a = __floats2half2_rn(lo[c].x, lo[c].y);
                __half2 h = __floats2half2_rn(hi[c].x, hi[c].y);
                alo[c] = *(unsigned *)&a;
                ahi[c] = *(unsigned *)&h;
            }
        }

        // ---- matvec: 16 k-chunks x 7 ngroups of HMMA.16816 (f16 -> f32 accum) ----
        float C[7][4];
        #pragma unroll
        for (int ng = 0; ng < 7; ng++) { C[ng][0] = C[ng][1] = C[ng][2] = C[ng][3] = 0.f; }

        #pragma unroll
        for (int c = 0; c < 16; c++) {
            #pragma unroll
            for (int ng = 0; ng < 7; ng++) {
                uint2 bb = wp[(c * 7 + ng) * 32];         // LDS.64, conflict-free
                asm("mma.sync.aligned.m16n8k16.row.col.f32.f16.f16.f32 "
                    "{%0,%1,%2,%3},{%4,%5,%6,%7},{%8,%9},{%0,%1,%2,%3};"
                    : "+f"(C[ng][0]), "+f"(C[ng][1]), "+f"(C[ng][2]), "+f"(C[ng][3])
                    : "r"(alo[c]), "r"(alo[c]), "r"(ahi[c]), "r"(ahi[c]),
                      "r"(bb.x), "r"(bb.y));
            }
        }

        // ---- export partial dots: C rows are replicated; lanes 0-3 hold all 8 cols ----
        if (lane < 4) {
            #pragma unroll
            for (int ng = 0; ng < 7; ng++) {
                red[w * DPAD + ng * 8 + lane * 2]     = C[ng][0];
                red[w * DPAD + ng * 8 + lane * 2 + 1] = C[ng][1];
            }
        }
        __syncthreads();

        // ---- epilogue: one thread per hidden unit ----
        if (tid < U) {
            float ct = g_c[t];
            float acc0 = ct * w0r[0] + br[0];
            float acc1 = ct * w0r[1] + br[1];
            float acc2 = ct * w0r[2] + br[2];
            float acc3 = ct * w0r[3] + br[3];
            #pragma unroll
            for (int ww = 0; ww < 8; ww++) {
                acc0 += red[ww * DPAD + tid * 4 + 0];
                acc1 += red[ww * DPAD + tid * 4 + 1];
                acc2 += red[ww * DPAD + tid * 4 + 2];
                acc3 += red[ww * DPAD + tid * 4 + 3];
            }
            float f  = sigm(acc0);
            float ii = sigm(acc1);
            float gg = tanh_fast(acc2);
            float oo = sigm(acc3);
            cx = f * cx + ii * gg;
            float h = oo * tanh_fast(cx);
            int j = ustart + tid;
            __stcg(out + (size_t)t * HID + j, h);
            if (t == S_LEN - 1) {
                out[SH_TOT + j]       = h;
                out[SH_TOT + HID + j] = cx;
            }
        }
        __syncthreads();

        // ---- grid barrier ----
        if (tid == 0) {
            __threadfence();
            bar_red(&g_bar);
            const unsigned tgt = (unsigned)NCTA * (unsigned)(t + 1);
            while (bar_ld(&g_bar) < tgt) { }
        }
        __syncthreads();
    }
}

// ---------------- launch ----------------
extern "C" void kernel_launch(void *const *d_in, const int *in_sizes, int n_in,
                              void *d_out, int out_size) {
    const float *inputs = nullptr, *cw = nullptr, *cb = nullptr, *wg = nullptr, *bg = nullptr;
    for (int i = 0; i < n_in; i++) {
        switch (in_sizes[i]) {
            case S_LEN * 4:        inputs = (const float *)d_in[i]; break;
            case 4:                cw     = (const float *)d_in[i]; break;
            case 1:                cb     = (const float *)d_in[i]; break;
            case 2049 * 4 * HID:   wg     = (const float *)d_in[i]; break;
            case 4 * HID:          bg     = (const float *)d_in[i]; break;
        }
    }
    float *out = (float *)d_out;

    static bool attr_set = false;
    if (!attr_set) {
        cudaFuncSetAttribute(lstm_main, cudaFuncAttributeMaxDynamicSharedMemorySize, SMEM_BYTES);
        attr_set = true;
    }

    prep_frag<<<(int)(((size_t)NCTA * U2_PER_CTA + 255) / 256), 256>>>(wg);
    prep_small<<<16, 256>>>(inputs, cw, cb, wg, bg);
    lstm_main<<<NCTA, NTHR, SMEM_BYTES>>>(out);
}

// round 3
// speedup vs baseline: 1.5006x; 1.1202x over previous
#include <cuda_runtime.h>
#include <cuda_fp16.h>

// ---------------- problem constants ----------------
#define S_LEN   4096
#define HID     2048
#define NCTA    148
#define NTHR    256
#define M_TOT   64            // mmas per warp per step (k chunks of 16 in this warp's k-half)
#define R_REG   32            // mmas whose A fragments live in registers
#define M_SMEM  (M_TOT - R_REG)
#define SMEM_W_BYTES (8 * M_SMEM * 32 * 16)          // 131072: SMEM-resident A fragments
#define SMEM_HX_BYTES 4096                            // f16 B-fragment image of hx
#define SMEM_BYTES (SMEM_W_BYTES + SMEM_HX_BYTES + 2 * 64 * 4)
#define SH_TOT  (S_LEN * HID)

// ---------------- device scratch ----------------
__device__ uint4    g_wA[(size_t)NCTA * 8 * M_TOT * 32]; // A-fragment-ordered fp16 weights
__device__ float    g_c[S_LEN];
__device__ float    g_w0[HID * 4];
__device__ float    g_bias[HID * 4];
__device__ unsigned g_bar;

// ---------------- helpers ----------------
__device__ __forceinline__ unsigned bar_ld(const unsigned *p) {
    unsigned v; asm volatile("ld.acquire.gpu.global.u32 %0,[%1];" : "=r"(v) : "l"(p)); return v;
}
__device__ __forceinline__ void bar_red(unsigned *p) {
    asm volatile("red.release.gpu.global.add.u32 [%0],1;" :: "l"(p));
}
__device__ __forceinline__ float sigm(float x)      { return 1.f / (1.f + __expf(-x)); }
__device__ __forceinline__ float tanh_fast(float x) { return 2.f / (1.f + __expf(-2.f * x)) - 1.f; }
__device__ __forceinline__ unsigned h2pack(float x, float y) {
    __half2 h = __floats2half2_rn(x, y); return *(unsigned *)&h;
}

// ---------------- prep: A-fragment-ordered weight image ----------------
// Entry (b, w, m, lane): warp w -> m-group g=w&3 (dots g*16..+15), k-half h=w>>2.
// mma m covers k chunk = h*1024 + m*16. Fragment (row-major A, m16k16):
//   a0={W[d0][kb],W[d0][kb+1]} a1={W[d1][kb],W[d1][kb+1]}
//   a2={W[d0][kb+8],W[d0][kb+9]} a3={W[d1][kb+8],W[d1][kb+9]}
// d0=g*16+(lane>>2), d1=d0+8, kb=h*1024+m*16+(lane&3)*2.
// W[d][k]=w_gates[(1+k)*8192 + (d&3)*2048 + ustart + (d>>2)], zero for d>=4U.
__global__ void prep_frag(const float *__restrict__ wg) {
    size_t idx = (size_t)blockIdx.x * 256 + threadIdx.x;
    if (idx >= (size_t)NCTA * 8 * M_TOT * 32) return;
    int lane = (int)(idx & 31);
    int m = (int)((idx >> 5) & (M_TOT - 1));
    int w = (int)((idx >> 11) & 7);
    int b = (int)(idx >> 14);
    int g = w & 3, h = w >> 2;
    int ustart = b * 13 + min(b, 124);
    int U4 = ((b < 124) ? 14 : 13) * 4;
    int d0 = g * 16 + (lane >> 2);
    int d1 = d0 + 8;
    int kb = h * 1024 + m * 16 + (lane & 3) * 2;

    auto W = [&](int d, int k) -> float {
        if (d >= U4) return 0.f;
        return wg[(size_t)(1 + k) * (4 * HID) + (d & 3) * HID + ustart + (d >> 2)];
    };
    uint4 v;
    v.x = h2pack(W(d0, kb),     W(d0, kb + 1));
    v.y = h2pack(W(d1, kb),     W(d1, kb + 1));
    v.z = h2pack(W(d0, kb + 8), W(d0, kb + 9));
    v.w = h2pack(W(d1, kb + 8), W(d1, kb + 9));
    g_wA[idx] = v;
}

// ---------------- prep: conv scalars, row-0 weights, biases, barrier reset ----------------
__global__ void prep_small(const float *__restrict__ in, const float *__restrict__ cw,
                           const float *__restrict__ cb, const float *__restrict__ wg,
                           const float *__restrict__ bg) {
    int tid = blockIdx.x * blockDim.x + threadIdx.x;
    if (tid < S_LEN) {
        float a = in[tid * 4 + 0] * cw[0] + in[tid * 4 + 1] * cw[1]
                + in[tid * 4 + 2] * cw[2] + in[tid * 4 + 3] * cw[3] + cb[0];
        g_c[tid] = 1.f / (1.f + __expf(-a));
    }
    for (int k = tid; k < 4 * HID; k += gridDim.x * blockDim.x) {
        int g = k & 3, j = k >> 2;
        g_w0[k]   = wg[g * HID + j];
        g_bias[k] = bg[g * HID + j];
    }
    if (tid == 0 && blockIdx.x == 0) g_bar = 0;
}

// ---------------- main persistent LSTM kernel ----------------
__global__ __launch_bounds__(NTHR, 1) void lstm_main(float *__restrict__ out) {
    extern __shared__ unsigned char smem[];
    uint4    *wsall = (uint4 *)smem;                             // [8][M_SMEM][32]
    uint4    *hx4   = (uint4 *)(smem + SMEM_W_BYTES);            // [64 cpair][4 cl]
    unsigned *hxw   = (unsigned *)hx4;
    float    *red   = (float *)(smem + SMEM_W_BYTES + SMEM_HX_BYTES); // [2][64]

    const int b = blockIdx.x;
    const int ustart = b * 13 + min(b, 124);
    const int U = (b < 124) ? 14 : 13;
    const int tid  = threadIdx.x;
    const int w    = tid >> 5;
    const int lane = tid & 31;
    const int g    = w & 3;
    const int h    = w >> 2;
    const int kc   = lane & 3;

    // Load this warp's A fragments: first R_REG to registers, rest to SMEM.
    const uint4 *gsrc = g_wA + ((size_t)(b * 8 + w) * M_TOT) * 32 + lane;
    uint4 areg[R_REG];
    #pragma unroll
    for (int m = 0; m < R_REG; m++) areg[m] = gsrc[(size_t)m * 32];
    uint4 *wsw = wsall + (w * M_SMEM) * 32 + lane;
    #pragma unroll
    for (int m = 0; m < M_SMEM; m++) wsw[m * 32] = gsrc[(size_t)(R_REG + m) * 32];

    float w0r[4], br[4], cx = 0.f;
    if (tid < U) {
        #pragma unroll
        for (int gg = 0; gg < 4; gg++) {
            w0r[gg] = g_w0[(ustart + tid) * 4 + gg];
            br[gg]  = g_bias[(ustart + tid) * 4 + gg];
        }
    }
    __syncthreads();

    const uint4 *hxp = hx4 + (h * 32) * 4 + kc;   // this warp's k-half, this lane's class

    for (int t = 0; t < S_LEN; t++) {
        // ---- stage hx(t-1) into SMEM as B-fragment-ordered f16 ----
        {
            unsigned v0, v1, v2, v3;
            if (t == 0) { v0 = v1 = v2 = v3 = 0u; }
            else {
                const float4 *p = (const float4 *)(out + (size_t)(t - 1) * HID) + tid * 2;
                float4 fa = p[0], fb = p[1];
                v0 = h2pack(fa.x, fa.y); v1 = h2pack(fa.z, fa.w);
                v2 = h2pack(fb.x, fb.y); v3 = h2pack(fb.z, fb.w);
            }
            int c = tid >> 1, hf = tid & 1;
            int base = (c >> 1) * 16 + (c & 1) * 2 + hf;   // word index
            hxw[base]      = v0;
            hxw[base + 4]  = v1;
            hxw[base + 8]  = v2;
            hxw[base + 12] = v3;
        }
        __syncthreads();

        // ---- matvec: 64 HMMA.16816, weights in A, hx replicated in B ----
        float e0 = 0.f, e1 = 0.f, e2 = 0.f, e3 = 0.f;   // even-chunk accum
        float o0 = 0.f, o1 = 0.f, o2 = 0.f, o3 = 0.f;   // odd-chunk accum
        uint4 bv;
        #pragma unroll
        for (int m = 0; m < M_TOT; m++) {
            if ((m & 1) == 0) bv = hxp[(m >> 1) * 4];
            uint4 av = (m < R_REG) ? areg[m] : wsw[(m - R_REG) * 32];
            if ((m & 1) == 0) {
                asm("mma.sync.aligned.m16n8k16.row.col.f32.f16.f16.f32 "
                    "{%0,%1,%2,%3},{%4,%5,%6,%7},{%8,%9},{%0,%1,%2,%3};"
                    : "+f"(e0), "+f"(e1), "+f"(e2), "+f"(e3)
                    : "r"(av.x), "r"(av.y), "r"(av.z), "r"(av.w),
                      "r"(bv.x), "r"(bv.y));
            } else {
                asm("mma.sync.aligned.m16n8k16.row.col.f32.f16.f16.f32 "
                    "{%0,%1,%2,%3},{%4,%5,%6,%7},{%8,%9},{%0,%1,%2,%3};"
                    : "+f"(o0), "+f"(o1), "+f"(o2), "+f"(o3)
                    : "r"(av.x), "r"(av.y), "r"(av.z), "r"(av.w),
                      "r"(bv.z), "r"(bv.w));
            }
        }

        // ---- export: lanes with col 0 hold rows lane>>2 and lane>>2+8 ----
        if ((lane & 3) == 0) {
            int r = lane >> 2;
            red[h * 64 + g * 16 + r]     = e0 + o0;
            red[h * 64 + g * 16 + 8 + r] = e2 + o2;
        }
        __syncthreads();

        // ---- epilogue (warp 0) + grid barrier ----
        if (w == 0) {
            if (tid < U) {
                float ct = g_c[t];
                float a0 = red[tid * 4 + 0] + red[64 + tid * 4 + 0] + ct * w0r[0] + br[0];
                float a1 = red[tid * 4 + 1] + red[64 + tid * 4 + 1] + ct * w0r[1] + br[1];
                float a2 = red[tid * 4 + 2] + red[64 + tid * 4 + 2] + ct * w0r[2] + br[2];
                float a3 = red[tid * 4 + 3] + red[64 + tid * 4 + 3] + ct * w0r[3] + br[3];
                float f  = sigm(a0);
                float ii = sigm(a1);
                float gg = tanh_fast(a2);
                float oo = sigm(a3);
                cx = f * cx + ii * gg;
                float hv = oo * tanh_fast(cx);
                int j = ustart + tid;
                __stcg(out + (size_t)t * HID + j, hv);
                if (t == S_LEN - 1) {
                    out[SH_TOT + j]       = hv;
                    out[SH_TOT + HID + j] = cx;
                }
            }
            __syncwarp();
            if (tid == 0) {
                bar_red(&g_bar);
                const unsigned tgt = (unsigned)NCTA * (unsigned)(t + 1);
                while (bar_ld(&g_bar) < tgt) { }
            }
        }
        __syncthreads();
    }
}

// ---------------- launch ----------------
extern "C" void kernel_launch(void *const *d_in, const int *in_sizes, int n_in,
                              void *d_out, int out_size) {
    const float *inputs = nullptr, *cw = nullptr, *cb = nullptr, *wg = nullptr, *bg = nullptr;
    for (int i = 0; i < n_in; i++) {
        switch (in_sizes[i]) {
            case S_LEN * 4:        inputs = (const float *)d_in[i]; break;
            case 4:                cw     = (const float *)d_in[i]; break;
            case 1:                cb     = (const float *)d_in[i]; break;
            case 2049 * 4 * HID:   wg     = (const float *)d_in[i]; break;
            case 4 * HID:          bg     = (const float *)d_in[i]; break;
        }
    }
    float *out = (float *)d_out;

    static bool attr_set = false;
    if (!attr_set) {
        cudaFuncSetAttribute(lstm_main, cudaFuncAttributeMaxDynamicSharedMemorySize, SMEM_BYTES);
        attr_set = true;
    }

    size_t nent = (size_t)NCTA * 8 * M_TOT * 32;
    prep_frag<<<(int)((nent + 255) / 256), 256>>>(wg);
    prep_small<<<16, 256>>>(inputs, cw, cb, wg, bg);
    lstm_main<<<NCTA, NTHR, SMEM_BYTES>>>(out);
}

// round 6
// speedup vs baseline: 1.5664x; 1.0438x over previous
#include <cuda_runtime.h>
#include <cuda_fp16.h>

// ---------------- problem constants ----------------
#define S_LEN   4096
#define HID     2048
#define NCTA    148
#define NTHR    256
#define M_TOT   64            // mmas per warp per step
#define R_REG   48            // mmas whose A fragments live in registers
#define M_SMEM  (M_TOT - R_REG)
#define SMEM_W_BYTES (8 * M_SMEM * 32 * 16)
#define SMEM_HX_BYTES 4096
#define SMEM_BYTES (SMEM_W_BYTES + SMEM_HX_BYTES + 2 * 64 * 4)
#define SH_TOT  (S_LEN * HID)
#define NFRAG   ((size_t)NCTA * 8 * M_TOT * 32)

// ---------------- device scratch ----------------
__device__ uint4    g_wA[NFRAG];     // A-fragment-ordered fp16 weights
__device__ float    g_c[S_LEN];
__device__ float    g_w0[HID * 4];
__device__ float    g_bias[HID * 4];
__device__ unsigned g_bar;           // monotonic grid barrier counter

// ---------------- helpers ----------------
__device__ __forceinline__ unsigned bar_ld(const unsigned *p) {
    unsigned v; asm volatile("ld.acquire.gpu.global.u32 %0,[%1];" : "=r"(v) : "l"(p)); return v;
}
__device__ __forceinline__ void bar_red(unsigned *p) {
    asm volatile("red.release.gpu.global.add.u32 [%0],1;" :: "l"(p));
}
__device__ __forceinline__ float sigm(float x)      { return 1.f / (1.f + __expf(-x)); }
__device__ __forceinline__ float tanh_fast(float x) { return 2.f / (1.f + __expf(-2.f * x)) - 1.f; }
__device__ __forceinline__ unsigned h2pack(float x, float y) {
    __half2 h = __floats2half2_rn(x, y); return *(unsigned *)&h;
}

// ---------------- single merged prep kernel ----------------
__global__ void prep_all(const float *__restrict__ wg, const float *__restrict__ in,
                         const float *__restrict__ cw, const float *__restrict__ cb,
                         const float *__restrict__ bg) {
    size_t idx = (size_t)blockIdx.x * 256 + threadIdx.x;

    if (idx < NFRAG) {
        int lane = (int)(idx & 31);
        int m = (int)((idx >> 5) & (M_TOT - 1));
        int w = (int)((idx >> 11) & 7);
        int b = (int)(idx >> 14);
        int g = w & 3, h = w >> 2;
        int ustart = b * 13 + min(b, 124);
        int U4 = ((b < 124) ? 14 : 13) * 4;
        int d0 = g * 16 + (lane >> 2);
        int d1 = d0 + 8;
        int kb = h * 1024 + m * 16 + (lane & 3) * 2;
        auto W = [&](int d, int k) -> float {
            if (d >= U4) return 0.f;
            return wg[(size_t)(1 + k) * (4 * HID) + (d & 3) * HID + ustart + (d >> 2)];
        };
        uint4 v;
        v.x = h2pack(W(d0, kb),     W(d0, kb + 1));
        v.y = h2pack(W(d1, kb),     W(d1, kb + 1));
        v.z = h2pack(W(d0, kb + 8), W(d0, kb + 9));
        v.w = h2pack(W(d1, kb + 8), W(d1, kb + 9));
        g_wA[idx] = v;
    }
    if (idx < S_LEN) {
        float a = in[idx * 4 + 0] * cw[0] + in[idx * 4 + 1] * cw[1]
                + in[idx * 4 + 2] * cw[2] + in[idx * 4 + 3] * cw[3] + cb[0];
        g_c[idx] = 1.f / (1.f + __expf(-a));
    }
    if (idx < 4 * HID) {
        int g = (int)idx & 3, j = (int)idx >> 2;
        g_w0[idx]   = wg[g * HID + j];
        g_bias[idx] = bg[g * HID + j];
    }
    if (idx == 0) g_bar = 0;
}

// ---------------- main persistent LSTM kernel ----------------
__global__ __launch_bounds__(NTHR, 1) void lstm_main(float *__restrict__ out) {
    extern __shared__ unsigned char smem[];
    uint4    *wsall = (uint4 *)smem;                                   // [8][M_SMEM][32]
    unsigned *hxw   = (unsigned *)(smem + SMEM_W_BYTES);               // 1024 words
    uint4    *hx4   = (uint4 *)hxw;
    float    *red   = (float *)(smem + SMEM_W_BYTES + SMEM_HX_BYTES);  // [2][64]

    const int b = blockIdx.x;
    const int ustart = b * 13 + min(b, 124);
    const int U = (b < 124) ? 14 : 13;
    const int tid  = threadIdx.x;
    const int w    = tid >> 5;
    const int lane = tid & 31;
    const int g    = w & 3;
    const int h    = w >> 2;
    const int kc   = lane & 3;

    // Load this warp's A fragments: first R_REG to registers, rest to SMEM.
    const uint4 *gsrc = g_wA + ((size_t)(b * 8 + w) * M_TOT) * 32 + lane;
    uint4 areg[R_REG];
    #pragma unroll
    for (int m = 0; m < R_REG; m++) areg[m] = gsrc[(size_t)m * 32];
    uint4 *wsw = wsall + (w * M_SMEM) * 32 + lane;
    #pragma unroll
    for (int m = 0; m < M_SMEM; m++) wsw[m * 32] = gsrc[(size_t)(R_REG + m) * 32];

    float w0r[4], br[4], cx = 0.f;
    if (tid < U) {
        #pragma unroll
        for (int gg = 0; gg < 4; gg++) {
            w0r[gg] = g_w0[(ustart + tid) * 4 + gg];
            br[gg]  = g_bias[(ustart + tid) * 4 + gg];
        }
    }
    __syncthreads();

    const uint4 *hxp = hx4 + (h * 32) * 4 + kc;

    for (int t = 0; t < S_LEN; t++) {
        // ---- stage hx(t-1) from out row into SMEM as B-fragment-ordered f16 ----
        {
            unsigned v0, v1, v2, v3;
            if (t == 0) { v0 = v1 = v2 = v3 = 0u; }
            else {
                const float4 *p = (const float4 *)(out + (size_t)(t - 1) * HID) + tid * 2;
                float4 fa = p[0], fb = p[1];
                v0 = h2pack(fa.x, fa.y); v1 = h2pack(fa.z, fa.w);
                v2 = h2pack(fb.x, fb.y); v3 = h2pack(fb.z, fb.w);
            }
            int c = tid >> 1, hf = tid & 1;
            int base = (c >> 1) * 16 + (c & 1) * 2 + hf;
            hxw[base]      = v0;
            hxw[base + 4]  = v1;
            hxw[base + 8]  = v2;
            hxw[base + 12] = v3;
        }
        __syncthreads();

        // ---- matvec: 64 HMMA.16816 per warp, weights in A, hx replicated in B ----
        float e0 = 0.f, e1 = 0.f, e2 = 0.f, e3 = 0.f;
        float o0 = 0.f, o1 = 0.f, o2 = 0.f, o3 = 0.f;
        uint4 bv;
        #pragma unroll
        for (int m = 0; m < M_TOT; m++) {
            if ((m & 1) == 0) bv = hxp[(m >> 1) * 4];
            uint4 av = (m < R_REG) ? areg[m] : wsw[(m - R_REG) * 32];
            if ((m & 1) == 0) {
                asm("mma.sync.aligned.m16n8k16.row.col.f32.f16.f16.f32 "
                    "{%0,%1,%2,%3},{%4,%5,%6,%7},{%8,%9},{%0,%1,%2,%3};"
                    : "+f"(e0), "+f"(e1), "+f"(e2), "+f"(e3)
                    : "r"(av.x), "r"(av.y), "r"(av.z), "r"(av.w),
                      "r"(bv.x), "r"(bv.y));
            } else {
                asm("mma.sync.aligned.m16n8k16.row.col.f32.f16.f16.f32 "
                    "{%0,%1,%2,%3},{%4,%5,%6,%7},{%8,%9},{%0,%1,%2,%3};"
                    : "+f"(o0), "+f"(o1), "+f"(o2), "+f"(o3)
                    : "r"(av.x), "r"(av.y), "r"(av.z), "r"(av.w),
                      "r"(bv.z), "r"(bv.w));
            }
        }

        // ---- export partial dots ----
        if ((lane & 3) == 0) {
            int r = lane >> 2;
            red[h * 64 + g * 16 + r]     = e0 + o0;
            red[h * 64 + g * 16 + 8 + r] = e2 + o2;
        }
        __syncthreads();

        // ---- epilogue (warp 0) + grid barrier (r3-proven) ----
        if (w == 0) {
            if (tid < U) {
                float ct = g_c[t];
                float a0 = red[tid * 4 + 0] + red[64 + tid * 4 + 0] + ct * w0r[0] + br[0];
                float a1 = red[tid * 4 + 1] + red[64 + tid * 4 + 1] + ct * w0r[1] + br[1];
                float a2 = red[tid * 4 + 2] + red[64 + tid * 4 + 2] + ct * w0r[2] + br[2];
                float a3 = red[tid * 4 + 3] + red[64 + tid * 4 + 3] + ct * w0r[3] + br[3];
                float f  = sigm(a0);
                float ii = sigm(a1);
                float gg = tanh_fast(a2);
                float oo = sigm(a3);
                cx = f * cx + ii * gg;
                float hv = oo * tanh_fast(cx);
                int j = ustart + tid;
                __stcg(out + (size_t)t * HID + j, hv);
                if (t == S_LEN - 1) {
                    out[SH_TOT + j]       = hv;
                    out[SH_TOT + HID + j] = cx;
                }
            }
            __syncwarp();
            if (tid == 0) {
                __threadfence();
                bar_red(&g_bar);
                const unsigned tgt = (unsigned)NCTA * (unsigned)(t + 1);
                while (bar_ld(&g_bar) < tgt) { }
            }
        }
        __syncthreads();
    }
}

// ---------------- launch ----------------
extern "C" void kernel_launch(void *const *d_in, const int *in_sizes, int n_in,
                              void *d_out, int out_size) {
    const float *inputs = nullptr, *cw = nullptr, *cb = nullptr, *wg = nullptr, *bg = nullptr;
    for (int i = 0; i < n_in; i++) {
        switch (in_sizes[i]) {
            case S_LEN * 4:        inputs = (const float *)d_in[i]; break;
            case 4:                cw     = (const float *)d_in[i]; break;
            case 1:                cb     = (const float *)d_in[i]; break;
            case 2049 * 4 * HID:   wg     = (const float *)d_in[i]; break;
            case 4 * HID:          bg     = (const float *)d_in[i]; break;
        }
    }
    float *out = (float *)d_out;

    static bool attr_set = false;
    if (!attr_set) {
        cudaFuncSetAttribute(lstm_main, cudaFuncAttributeMaxDynamicSharedMemorySize, SMEM_BYTES);
        attr_set = true;
    }

    prep_all<<<(int)((NFRAG + 255) / 256), 256>>>(wg, inputs, cw, cb, bg);
    lstm_main<<<NCTA, NTHR, SMEM_BYTES>>>(out);
}

// round 7
// speedup vs baseline: 1.6085x; 1.0268x over previous
#include <cuda_runtime.h>
#include <cuda_fp16.h>

// ---------------- problem constants ----------------
#define S_LEN   4096
#define HID     2048
#define NCTA    148
#define NTHR    256
#define M_TOT   64            // mmas per warp per step
#define R_REG   40            // mmas whose A fragments live in registers
#define M_SMEM  (M_TOT - R_REG)
#define SMEM_W_BYTES (8 * M_SMEM * 32 * 16)          // 98304
#define SMEM_HX_BYTES 4096
#define SMEM_BYTES (SMEM_W_BYTES + SMEM_HX_BYTES + 2 * 64 * 4)
#define SH_TOT  (S_LEN * HID)
#define NFRAG   ((size_t)NCTA * 8 * M_TOT * 32)

// ---------------- device scratch ----------------
__device__ uint4    g_wA[NFRAG];     // A-fragment-ordered fp16 weights
__device__ __align__(16) unsigned short g_img[(size_t)S_LEN * HID]; // f16 hx rows, B-frag permuted
__device__ float    g_c[S_LEN];
__device__ float    g_w0[HID * 4];
__device__ float    g_bias[HID * 4];
__device__ unsigned g_bar;           // monotonic grid barrier counter

// ---------------- helpers ----------------
__device__ __forceinline__ unsigned bar_ld(const unsigned *p) {
    unsigned v; asm volatile("ld.acquire.gpu.global.u32 %0,[%1];" : "=r"(v) : "l"(p)); return v;
}
__device__ __forceinline__ void bar_red(unsigned *p) {
    asm volatile("red.release.gpu.global.add.u32 [%0],1;" :: "l"(p));
}
__device__ __forceinline__ uint4 ld_cg4(const void *p) {
    uint4 v;
    asm volatile("ld.global.cg.v4.u32 {%0,%1,%2,%3},[%4];"
                 : "=r"(v.x), "=r"(v.y), "=r"(v.z), "=r"(v.w) : "l"(p));
    return v;
}
__device__ __forceinline__ float sigm(float x)      { return 1.f / (1.f + __expf(-x)); }
__device__ __forceinline__ float tanh_fast(float x) { return 2.f / (1.f + __expf(-2.f * x)) - 1.f; }
__device__ __forceinline__ unsigned h2pack(float x, float y) {
    __half2 h = __floats2half2_rn(x, y); return *(unsigned *)&h;
}

// ---------------- single merged prep kernel ----------------
__global__ void prep_all(const float *__restrict__ wg, const float *__restrict__ in,
                         const float *__restrict__ cw, const float *__restrict__ cb,
                         const float *__restrict__ bg) {
    size_t idx = (size_t)blockIdx.x * 256 + threadIdx.x;

    if (idx < NFRAG) {
        int lane = (int)(idx & 31);
        int m = (int)((idx >> 5) & (M_TOT - 1));
        int w = (int)((idx >> 11) & 7);
        int b = (int)(idx >> 14);
        int g = w & 3, h = w >> 2;
        int ustart = b * 13 + min(b, 124);
        int U4 = ((b < 124) ? 14 : 13) * 4;
        int d0 = g * 16 + (lane >> 2);
        int d1 = d0 + 8;
        int kb = h * 1024 + m * 16 + (lane & 3) * 2;
        auto W = [&](int d, int k) -> float {
            if (d >= U4) return 0.f;
            return wg[(size_t)(1 + k) * (4 * HID) + (d & 3) * HID + ustart + (d >> 2)];
        };
        uint4 v;
        v.x = h2pack(W(d0, kb),     W(d0, kb + 1));
        v.y = h2pack(W(d1, kb),     W(d1, kb + 1));
        v.z = h2pack(W(d0, kb + 8), W(d0, kb + 9));
        v.w = h2pack(W(d1, kb + 8), W(d1, kb + 9));
        g_wA[idx] = v;
    }
    if (idx < S_LEN) {
        float a = in[idx * 4 + 0] * cw[0] + in[idx * 4 + 1] * cw[1]
                + in[idx * 4 + 2] * cw[2] + in[idx * 4 + 3] * cw[3] + cb[0];
        g_c[idx] = 1.f / (1.f + __expf(-a));
    }
    if (idx < 4 * HID) {
        int g = (int)idx & 3, j = (int)idx >> 2;
        g_w0[idx]   = wg[g * HID + j];
        g_bias[idx] = bg[g * HID + j];
    }
    if (idx == 0) g_bar = 0;
}

// ---------------- main persistent LSTM kernel ----------------
__global__ __launch_bounds__(NTHR, 1) void lstm_main(float *__restrict__ out) {
    extern __shared__ unsigned char smem[];
    uint4    *wsall = (uint4 *)smem;                                   // [8][M_SMEM][32]
    unsigned *hxw   = (unsigned *)(smem + SMEM_W_BYTES);               // 1024 words
    uint4    *hx4   = (uint4 *)hxw;
    float    *red   = (float *)(smem + SMEM_W_BYTES + SMEM_HX_BYTES);  // [2][64]

    const int b = blockIdx.x;
    const int ustart = b * 13 + min(b, 124);
    const int U = (b < 124) ? 14 : 13;
    const int tid  = threadIdx.x;
    const int w    = tid >> 5;
    const int lane = tid & 31;
    const int g    = w & 3;
    const int h    = w >> 2;
    const int kc   = lane & 3;

    // Load this warp's A fragments: first R_REG to registers, rest to SMEM.
    const uint4 *gsrc = g_wA + ((size_t)(b * 8 + w) * M_TOT) * 32 + lane;
    uint4 areg[R_REG];
    #pragma unroll
    for (int m = 0; m < R_REG; m++) areg[m] = gsrc[(size_t)m * 32];
    uint4 *wsw = wsall + (w * M_SMEM) * 32 + lane;
    #pragma unroll
    for (int m = 0; m < M_SMEM; m++) wsw[m * 32] = gsrc[(size_t)(R_REG + m) * 32];

    float w0r[4], br[4], cx = 0.f;
    if (tid < U) {
        #pragma unroll
        for (int gg = 0; gg < 4; gg++) {
            w0r[gg] = g_w0[(ustart + tid) * 4 + gg];
            br[gg]  = g_bias[(ustart + tid) * 4 + gg];
        }
    }
    // precompute this thread's hx publish slot (B-frag permuted u16 address)
    int pub_off = 0;
    {
        int j = ustart + tid;
        int p = j >> 1;
        int wi = ((p >> 4) << 4) + (((p >> 3) & 1) << 1) + ((p >> 2) & 1) + ((p & 3) << 2);
        pub_off = wi * 2 + (j & 1);
    }
    __syncthreads();

    const uint4 *hxp = hx4 + (h * 32) * 4 + kc;

    for (int t = 0; t < S_LEN; t++) {
        // ---- stage hx(t-1): pre-permuted f16 image, identity copy GMEM->SMEM ----
        {
            uint4 v;
            if (t == 0) v = make_uint4(0u, 0u, 0u, 0u);
            else        v = ld_cg4((const uint4 *)(g_img + (size_t)(t - 1) * HID) + tid);
            ((uint4 *)hxw)[tid] = v;
        }
        __syncthreads();

        // ---- matvec: 64 HMMA.16816 per warp, 4 independent accumulator chains ----
        float c0[4] = {0.f, 0.f, 0.f, 0.f};
        float c1[4] = {0.f, 0.f, 0.f, 0.f};
        float c2[4] = {0.f, 0.f, 0.f, 0.f};
        float c3[4] = {0.f, 0.f, 0.f, 0.f};
        uint4 bv;
        #pragma unroll
        for (int m = 0; m < M_TOT; m++) {
            if ((m & 1) == 0) bv = hxp[(m >> 1) * 4];
            uint4 av = (m < R_REG) ? areg[m] : wsw[(m - R_REG) * 32];
            unsigned blo = (m & 1) ? bv.z : bv.x;
            unsigned bhi = (m & 1) ? bv.w : bv.y;
            float *C = ((m & 3) == 0) ? c0 : ((m & 3) == 1) ? c1 : ((m & 3) == 2) ? c2 : c3;
            asm("mma.sync.aligned.m16n8k16.row.col.f32.f16.f16.f32 "
                "{%0,%1,%2,%3},{%4,%5,%6,%7},{%8,%9},{%0,%1,%2,%3};"
                : "+f"(C[0]), "+f"(C[1]), "+f"(C[2]), "+f"(C[3])
                : "r"(av.x), "r"(av.y), "r"(av.z), "r"(av.w),
                  "r"(blo), "r"(bhi));
        }

        // ---- export partial dots ----
        if ((lane & 3) == 0) {
            int r = lane >> 2;
            red[h * 64 + g * 16 + r]     = c0[0] + c1[0] + c2[0] + c3[0];
            red[h * 64 + g * 16 + 8 + r] = c0[2] + c1[2] + c2[2] + c3[2];
        }
        __syncthreads();

        // ---- epilogue (warp 0): gates, state, publish f16 image, then barrier ----
        if (w == 0) {
            float hv = 0.f;
            if (tid < U) {
                float ct = g_c[t];
                float a0 = red[tid * 4 + 0] + red[64 + tid * 4 + 0] + ct * w0r[0] + br[0];
                float a1 = red[tid * 4 + 1] + red[64 + tid * 4 + 1] + ct * w0r[1] + br[1];
                float a2 = red[tid * 4 + 2] + red[64 + tid * 4 + 2] + ct * w0r[2] + br[2];
                float a3 = red[tid * 4 + 3] + red[64 + tid * 4 + 3] + ct * w0r[3] + br[3];
                float f  = sigm(a0);
                float ii = sigm(a1);
                float gg = tanh_fast(a2);
                float oo = sigm(a3);
                cx = f * cx + ii * gg;
                hv = oo * tanh_fast(cx);
                // publish pre-permuted f16 (visibility via fence+red below)
                unsigned short hb = __half_as_ushort(__float2half_rn(hv));
                asm volatile("st.global.cg.u16 [%0],%1;"
                             :: "l"(g_img + (size_t)t * HID + pub_off), "h"(hb));
            }
            __syncwarp();
            if (tid == 0) {
                __threadfence();
                bar_red(&g_bar);
            }
            // f32 output row: off the fence's drain set, no cross-SM ordering needed
            if (tid < U) {
                int j = ustart + tid;
                out[(size_t)t * HID + j] = hv;
                if (t == S_LEN - 1) {
                    out[SH_TOT + j]       = hv;
                    out[SH_TOT + HID + j] = cx;
                }
            }
            if (tid == 0) {
                const unsigned tgt = (unsigned)NCTA * (unsigned)(t + 1);
                while (bar_ld(&g_bar) < tgt) { }
            }
        }
        __syncthreads();
    }
}

// ---------------- launch ----------------
extern "C" void kernel_launch(void *const *d_in, const int *in_sizes, int n_in,
                              void *d_out, int out_size) {
    const float *inputs = nullptr, *cw = nullptr, *cb = nullptr, *wg = nullptr, *bg = nullptr;
    for (int i = 0; i < n_in; i++) {
        switch (in_sizes[i]) {
            case S_LEN * 4:        inputs = (const float *)d_in[i]; break;
            case 4:                cw     = (const float *)d_in[i]; break;
            case 1:                cb     = (const float *)d_in[i]; break;
            case 2049 * 4 * HID:   wg     = (const float *)d_in[i]; break;
            case 4 * HID:          bg     = (const float *)d_in[i]; break;
        }
    }
    float *out = (float *)d_out;

    static bool attr_set = false;
    if (!attr_set) {
        cudaFuncSetAttribute(lstm_main, cudaFuncAttributeMaxDynamicSharedMemorySize, SMEM_BYTES);
        attr_set = true;
    }

    prep_all<<<(int)((NFRAG + 255) / 256), 256>>>(wg, inputs, cw, cb, bg);
    lstm_main<<<NCTA, NTHR, SMEM_BYTES>>>(out);
}